// round 3
// baseline (speedup 1.0000x reference)
#include <cuda_runtime.h>

typedef unsigned long long u64;

#define Dd 128
#define Bb 4096
#define NT 32            // samples per CTA
#define TMr 8            // rows per thread (strided by 16)
#define TNc 4            // samples per thread (2x f32x2)
#define NTHREADS 128     // (128/TMr)=16 row-groups * (NT/TNc)=8 col-groups
#define KTERMS 20        // Taylor terms; remainder ~4e-13
#define VP 34            // V row pitch in floats (even -> 8B-aligned pairs)

__device__ __forceinline__ u64 pk2(float a, float b) {
    u64 r; asm("mov.b64 %0, {%1, %2};" : "=l"(r) : "f"(a), "f"(b)); return r;
}
__device__ __forceinline__ float2 upk2(u64 v) {
    float2 r; asm("mov.b64 {%0, %1}, %2;" : "=f"(r.x), "=f"(r.y) : "l"(v)); return r;
}
__device__ __forceinline__ u64 fma2(u64 a, u64 b, u64 c) {
    u64 d; asm("fma.rn.f32x2 %0, %1, %2, %3;" : "=l"(d) : "l"(a), "l"(b), "l"(c)); return d;
}
__device__ __forceinline__ u64 mul2(u64 a, u64 b) {
    u64 d; asm("mul.rn.f32x2 %0, %1, %2;" : "=l"(d) : "l"(a), "l"(b)); return d;
}
__device__ __forceinline__ u64 add2(u64 a, u64 b) {
    u64 d; asm("add.rn.f32x2 %0, %1, %2;" : "=l"(d) : "l"(a), "l"(b)); return d;
}

// y_b = exp(t_b * W) x_b + bias * t_b ; ljd_b = diag(W) * t_b
// Taylor iteration: v_k = (t_b / k) * W * v_{k-1}, y = sum v_k.
// Each CTA: W packed-duplicated in SMEM (transposed), 32-sample V slab
// double-buffered in SMEM, 20 on-chip 128x32x128 GEMM iterations.
__global__ void __launch_bounds__(NTHREADS, 1) affexp_kernel(
    const float* __restrict__ x, const float* __restrict__ t,
    const float* __restrict__ W, const float* __restrict__ bias,
    float* __restrict__ out)
{
    extern __shared__ float sm[];
    u64*   Wp = (u64*)sm;              // Wp[j*128 + i] = (W[i][j], W[i][j])  (131072 B)
    float* V0 = sm + 2 * Dd * Dd;      // V[d*VP + s]
    float* V1 = V0 + Dd * VP;

    const int tid = threadIdx.x;
    const int rg  = tid & 15;          // row group: rows i = rg + 16*r
    const int cg  = tid >> 4;          // col group: samples sc..sc+3
    const int s0  = blockIdx.x * NT;
    const int scb = cg * TNc;

    // Load W transposed + packed: global read coalesced (idx = i*128 + j).
    for (int idx = tid; idx < Dd * Dd; idx += NTHREADS) {
        int i = idx >> 7, j = idx & 127;
        float w = W[idx];
        Wp[j * Dd + i] = pk2(w, w);
    }
    // Load x tile: coalesced global read, V stored feature-major.
    for (int idx = tid; idx < NT * Dd; idx += NTHREADS) {
        int s = idx >> 7, d = idx & 127;
        V0[d * VP + s] = x[(size_t)(s0 + s) * Dd + d];
    }
    __syncthreads();

    float ts[TNc];
    #pragma unroll
    for (int c = 0; c < TNc; c++) ts[c] = t[s0 + scb + c];

    // y accumulator initialized with v0 = x tile.
    u64 yacc[TMr][2];
    #pragma unroll
    for (int r = 0; r < TMr; r++) {
        int i = rg + 16 * r;
        #pragma unroll
        for (int cp = 0; cp < 2; cp++)
            yacc[r][cp] = *(const u64*)&V0[i * VP + scb + 2 * cp];
    }

    float* Vc = V0;
    float* Vn = V1;
    #pragma unroll 1
    for (int k = 1; k <= KTERMS; k++) {
        float invk = 1.0f / (float)k;
        u64 sc2[2] = { pk2(ts[0] * invk, ts[1] * invk),
                       pk2(ts[2] * invk, ts[3] * invk) };

        u64 acc[TMr][2];
        #pragma unroll
        for (int r = 0; r < TMr; r++) { acc[r][0] = 0ull; acc[r][1] = 0ull; }

        // u = W * v for this tile: FMA2-pipe-bound inner loop.
        #pragma unroll 8
        for (int j = 0; j < Dd; j++) {
            u64 vp0 = *(const u64*)&Vc[j * VP + scb];
            u64 vp1 = *(const u64*)&Vc[j * VP + scb + 2];
            const u64* wrow = &Wp[j * Dd + rg];
            #pragma unroll
            for (int r = 0; r < TMr; r++) {
                u64 w2 = wrow[16 * r];
                acc[r][0] = fma2(w2, vp0, acc[r][0]);
                acc[r][1] = fma2(w2, vp1, acc[r][1]);
            }
        }

        // v_k = (t/k) * u ; y += v_k ; store for next iteration.
        #pragma unroll
        for (int r = 0; r < TMr; r++) {
            int i = rg + 16 * r;
            #pragma unroll
            for (int cp = 0; cp < 2; cp++) {
                u64 v = mul2(acc[r][cp], sc2[cp]);
                yacc[r][cp] = add2(yacc[r][cp], v);
                *(u64*)&Vn[i * VP + scb + 2 * cp] = v;
            }
        }
        __syncthreads();
        float* tmp = Vc; Vc = Vn; Vn = tmp;
    }

    // Epilogue: y += bias*t, and ljd = diag(W)*t. out = [y (B*D) | ljd (B*D)].
    #pragma unroll
    for (int r = 0; r < TMr; r++) {
        int i = rg + 16 * r;
        float bi  = bias[i];
        float wii = W[i * Dd + i];
        #pragma unroll
        for (int cp = 0; cp < 2; cp++) {
            float2 yv = upk2(yacc[r][cp]);
            int sA = s0 + scb + 2 * cp;
            out[(size_t)sA * Dd + i]           = yv.x + bi * ts[2 * cp];
            out[(size_t)(sA + 1) * Dd + i]     = yv.y + bi * ts[2 * cp + 1];
            out[(size_t)Bb * Dd + (size_t)sA * Dd + i]       = wii * ts[2 * cp];
            out[(size_t)Bb * Dd + (size_t)(sA + 1) * Dd + i] = wii * ts[2 * cp + 1];
        }
    }
}

extern "C" void kernel_launch(void* const* d_in, const int* in_sizes, int n_in,
                              void* d_out, int out_size) {
    const float* x    = (const float*)d_in[0];
    const float* t    = (const float*)d_in[1];
    const float* W    = (const float*)d_in[2];
    const float* bias = (const float*)d_in[3];
    float* out = (float*)d_out;

    size_t smem = (2 * Dd * Dd + 2 * Dd * VP) * sizeof(float);  // 165,888 B
    cudaFuncSetAttribute(affexp_kernel,
                         cudaFuncAttributeMaxDynamicSharedMemorySize, (int)smem);
    affexp_kernel<<<Bb / NT, NTHREADS, smem>>>(x, t, W, bias, out);
}

// round 5
// speedup vs baseline: 1.9397x; 1.9397x over previous
#include <cuda_runtime.h>
#include <cstdint>

#define Dd 128
#define Bb 4096
#define NT 32            // samples per CTA
#define NTHREADS 256     // 32 row-quads x 8 sample-groups; 2 warps/SMSP
#define KTERMS 13        // Taylor terms; truncation ~1e-6 global rel
#define VP 36            // V pitch in floats (multiple of 4 for v4 loads)

typedef unsigned long long u64;

static __device__ __forceinline__ uint32_t smem_u32(const void* p) {
    uint32_t a;
    asm("{ .reg .u64 t; cvta.to.shared.u64 t, %1; cvt.u32.u64 %0, t; }" : "=r"(a) : "l"(p));
    return a;
}
static __device__ __forceinline__ u64 pk2(float a, float b) {
    u64 r; asm("mov.b64 %0, {%1, %2};" : "=l"(r) : "f"(a), "f"(b)); return r;
}
static __device__ __forceinline__ void upk(u64 v, float& a, float& b) {
    asm("mov.b64 {%0, %1}, %2;" : "=f"(a), "=f"(b) : "l"(v));
}
static __device__ __forceinline__ u64 fma2(u64 a, u64 b, u64 c) {
    u64 d; asm("fma.rn.f32x2 %0, %1, %2, %3;" : "=l"(d) : "l"(a), "l"(b), "l"(c)); return d;
}
static __device__ __forceinline__ u64 mul2(u64 a, u64 b) {
    u64 d; asm("mul.rn.f32x2 %0, %1, %2;" : "=l"(d) : "l"(a), "l"(b)); return d;
}
static __device__ __forceinline__ u64 add2(u64 a, u64 b) {
    u64 d; asm("add.rn.f32x2 %0, %1, %2;" : "=l"(d) : "l"(a), "l"(b)); return d;
}

// y_b = exp(t_b W) x_b + bias t_b ; ljd = diag(W) t_b.
// Taylor: v_k = (t_b/k) W v_{k-1}, y = sum v_k. Per CTA: un-duplicated
// transposed W in SMEM (64KB); f32x2 lanes pair CONSECUTIVE ROWS so the W
// operand is one conflict-free LDS.128 (two register-pair-aligned f32x2
// operands) -> smem crossbar 40 cyc/j vs 64 for the duplicated-W layout.
__global__ void __launch_bounds__(NTHREADS, 1) affexp_kernel(
    const float* __restrict__ x, const float* __restrict__ t,
    const float* __restrict__ W, const float* __restrict__ bias,
    float* __restrict__ out)
{
    extern __shared__ float sm[];
    float* Wt = sm;                    // Wt[j*128 + i] = W[i][j]  (64 KB)
    float* V0 = sm + Dd * Dd;          // V[d*VP + s]
    float* V1 = V0 + Dd * VP;

    const int tid = threadIdx.x;
    const int rq  = tid & 31;          // row quad: rows d0..d0+3
    const int cg  = tid >> 5;          // warp == sample group (4 samples)
    const int d0  = rq * 4;
    const int scb = cg * 4;
    const int s0  = blockIdx.x * NT;

    // Transpose W into SMEM (coalesced global reads; one-time store conflicts ok).
    for (int idx = tid; idx < Dd * Dd; idx += NTHREADS) {
        int i = idx >> 7, j = idx & 127;
        Wt[j * Dd + i] = W[idx];
    }

    float ts[4];
    #pragma unroll
    for (int c = 0; c < 4; c++) ts[c] = t[s0 + scb + c];

    // v0 = x: y accumulator as row-pair u64s; V0 operand tile feature-major.
    u64 y[2][4];
    float4 xv[4];
    #pragma unroll
    for (int c = 0; c < 4; c++) {
        xv[c] = *(const float4*)&x[(size_t)(s0 + scb + c) * Dd + d0];
        y[0][c] = pk2(xv[c].x, xv[c].y);
        y[1][c] = pk2(xv[c].z, xv[c].w);
    }
    #pragma unroll
    for (int rr = 0; rr < 4; rr++) {
        float4 vs = make_float4(((const float*)&xv[0])[rr], ((const float*)&xv[1])[rr],
                                ((const float*)&xv[2])[rr], ((const float*)&xv[3])[rr]);
        *(float4*)&V0[(d0 + rr) * VP + scb] = vs;
    }
    __syncthreads();

    const uint32_t wb  = smem_u32(Wt) + d0 * 4;    // + j*512
    const uint32_t v0b = smem_u32(V0) + scb * 4;   // + j*144
    const uint32_t v1b = smem_u32(V1) + scb * 4;

    uint32_t vcb = v0b;
    float*   Vn  = V1;

    #pragma unroll 1
    for (int k = 1; k <= KTERMS; k++) {
        u64 acc[2][4];
        #pragma unroll
        for (int c = 0; c < 4; c++) { acc[0][c] = 0ull; acc[1][c] = 0ull; }

        // u = W * v : 1x LDS.128 (W, 2 row-pair operands) + 1x LDS.128 (V,
        // broadcast) + 4 dup movs (ALU pipe) + 8 FMA2 per thread per j.
        #pragma unroll 8
        for (int j = 0; j < Dd; j++) {
            u64 w01, w23;
            asm("ld.shared.v2.b64 {%0, %1}, [%2];"
                : "=l"(w01), "=l"(w23) : "r"(wb + j * 512));
            float f0, f1, f2, f3;
            asm("ld.shared.v4.b32 {%0, %1, %2, %3}, [%4];"
                : "=f"(f0), "=f"(f1), "=f"(f2), "=f"(f3) : "r"(vcb + j * 144));
            u64 vd0 = pk2(f0, f0), vd1 = pk2(f1, f1);
            u64 vd2 = pk2(f2, f2), vd3 = pk2(f3, f3);
            acc[0][0] = fma2(w01, vd0, acc[0][0]);
            acc[1][0] = fma2(w23, vd0, acc[1][0]);
            acc[0][1] = fma2(w01, vd1, acc[0][1]);
            acc[1][1] = fma2(w23, vd1, acc[1][1]);
            acc[0][2] = fma2(w01, vd2, acc[0][2]);
            acc[1][2] = fma2(w23, vd2, acc[1][2]);
            acc[0][3] = fma2(w01, vd3, acc[0][3]);
            acc[1][3] = fma2(w23, vd3, acc[1][3]);
        }

        // v_k = (t/k) * u ; y += v_k ; write v_k as next B operand.
        float invk = 1.0f / (float)k;
        u64 v[2][4];
        #pragma unroll
        for (int c = 0; c < 4; c++) {
            float cc = ts[c] * invk;
            u64 scd = pk2(cc, cc);
            v[0][c] = mul2(acc[0][c], scd);
            v[1][c] = mul2(acc[1][c], scd);
            y[0][c] = add2(y[0][c], v[0][c]);
            y[1][c] = add2(y[1][c], v[1][c]);
        }

        if (k < KTERMS) {
            float vf[4][4];   // [sample][row-in-quad]
            #pragma unroll
            for (int c = 0; c < 4; c++) {
                upk(v[0][c], vf[c][0], vf[c][1]);
                upk(v[1][c], vf[c][2], vf[c][3]);
            }
            #pragma unroll
            for (int rr = 0; rr < 4; rr++) {
                *(float4*)&Vn[(d0 + rr) * VP + scb] =
                    make_float4(vf[0][rr], vf[1][rr], vf[2][rr], vf[3][rr]);
            }
            __syncthreads();
            vcb = (Vn == V1) ? v1b : v0b;
            Vn  = (Vn == V1) ? V0  : V1;
        }
    }

    // Epilogue: out = [y + bias*t | diag(W)*t], both [B, D], float4 coalesced.
    float4 bv = *(const float4*)&bias[d0];
    float wd[4];
    #pragma unroll
    for (int rr = 0; rr < 4; rr++) wd[rr] = W[(size_t)(d0 + rr) * Dd + (d0 + rr)];

    #pragma unroll
    for (int c = 0; c < 4; c++) {
        float y0, y1, y2, y3;
        upk(y[0][c], y0, y1);
        upk(y[1][c], y2, y3);
        float tc = ts[c];
        size_t s = (size_t)(s0 + scb + c);
        *(float4*)&out[s * Dd + d0] =
            make_float4(y0 + bv.x * tc, y1 + bv.y * tc, y2 + bv.z * tc, y3 + bv.w * tc);
        *(float4*)&out[(size_t)Bb * Dd + s * Dd + d0] =
            make_float4(wd[0] * tc, wd[1] * tc, wd[2] * tc, wd[3] * tc);
    }
}

extern "C" void kernel_launch(void* const* d_in, const int* in_sizes, int n_in,
                              void* d_out, int out_size) {
    const float* x    = (const float*)d_in[0];
    const float* t    = (const float*)d_in[1];
    const float* W    = (const float*)d_in[2];
    const float* bias = (const float*)d_in[3];
    float* out = (float*)d_out;

    size_t smem = (Dd * Dd + 2 * Dd * VP) * sizeof(float);  // 102,400 B
    cudaFuncSetAttribute(affexp_kernel,
                         cudaFuncAttributeMaxDynamicSharedMemorySize, (int)smem);
    affexp_kernel<<<Bb / NT, NTHREADS, smem>>>(x, t, W, bias, out);
}

// round 6
// speedup vs baseline: 2.3409x; 1.2068x over previous
#include <cuda_runtime.h>
#include <cstdint>

#define Dd 128
#define Bb 4096
#define NT 32            // samples per CTA
#define NTHREADS 256     // 64 row-pairs x 4 sample-octets; 2 warps/SMSP
#define KTERMS 11        // Taylor terms; truncation ~5e-6 global rel (vs 1e-3)
#define WP 132           // Wt row pitch in floats (4-way store conflict, cf-free loads)
#define VP 36            // V row pitch in floats (16B-aligned rows: 144 = 9*16)

typedef unsigned long long u64;

static __device__ __forceinline__ uint32_t smem_u32(const void* p) {
    uint32_t a;
    asm("{ .reg .u64 t; cvta.to.shared.u64 t, %1; cvt.u32.u64 %0, t; }" : "=r"(a) : "l"(p));
    return a;
}
static __device__ __forceinline__ u64 pk2(float a, float b) {
    u64 r; asm("mov.b64 %0, {%1, %2};" : "=l"(r) : "f"(a), "f"(b)); return r;
}
static __device__ __forceinline__ void upk(u64 v, float& a, float& b) {
    asm("mov.b64 {%0, %1}, %2;" : "=f"(a), "=f"(b) : "l"(v));
}
static __device__ __forceinline__ u64 fma2(u64 a, u64 b, u64 c) {
    u64 d; asm("fma.rn.f32x2 %0, %1, %2, %3;" : "=l"(d) : "l"(a), "l"(b), "l"(c)); return d;
}
static __device__ __forceinline__ u64 mul2(u64 a, u64 b) {
    u64 d; asm("mul.rn.f32x2 %0, %1, %2;" : "=l"(d) : "l"(a), "l"(b)); return d;
}
static __device__ __forceinline__ u64 add2(u64 a, u64 b) {
    u64 d; asm("add.rn.f32x2 %0, %1, %2;" : "=l"(d) : "l"(a), "l"(b)); return d;
}

// y_b = exp(t_b W) x_b + bias t_b ; ljd = diag(W) t_b.
// Taylor: v_k = (t_b/k) W v_{k-1}, y = sum v_k.
// Thread tile 2 rows x 8 samples: per warp per j the W operand is 256B
// (2 wavefronts) amortized over 8 samples, V is a 32B broadcast (2 wf)
// -> 32 wf/j crossbar == 32 cyc/j FMA2 floor (balanced pipes).
__global__ void __launch_bounds__(NTHREADS, 1) affexp_kernel(
    const float* __restrict__ x, const float* __restrict__ t,
    const float* __restrict__ W, const float* __restrict__ bias,
    float* __restrict__ out)
{
    extern __shared__ float sm[];
    float* Wt = sm;                    // Wt[j*WP + i] = W[i][j]
    float* V0 = sm + Dd * WP;
    float* V1 = V0 + Dd * VP;
    float* st = V1 + Dd * VP;          // staged t values

    const int tid = threadIdx.x;
    const int rg  = tid & 63;          // row pair: d0 = 2*rg, d0+1
    const int oct = tid >> 6;          // sample octet: scb..scb+7
    const int d0  = rg * 2;
    const int scb = oct * 8;
    const int s0  = blockIdx.x * NT;

    // Transpose W: thread handles (j, row-quad); LDGs coalesced over j, float4 STS.
    for (int task = tid; task < Dd * 32; task += NTHREADS) {
        int j = task & 127, i = (task >> 7) * 4;
        float4 wv = make_float4(W[(i + 0) * Dd + j], W[(i + 1) * Dd + j],
                                W[(i + 2) * Dd + j], W[(i + 3) * Dd + j]);
        *(float4*)&Wt[j * WP + i] = wv;
    }
    // x tile -> V0 (feature-major), coalesced global reads.
    for (int idx = tid; idx < NT * Dd; idx += NTHREADS) {
        int s = idx >> 7, d = idx & 127;
        V0[d * VP + s] = x[(size_t)(s0 + s) * Dd + d];
    }
    if (tid < NT) st[tid] = t[s0 + tid];
    __syncthreads();

    // t as sample pairs.
    u64 tp[4];
    #pragma unroll
    for (int p = 0; p < 4; p++) tp[p] = pk2(st[scb + 2 * p], st[scb + 2 * p + 1]);

    const uint32_t wb  = smem_u32(Wt) + rg * 8;    // + j*528
    const uint32_t v0b = smem_u32(V0) + scb * 4;   // + j*144 (+16)
    const uint32_t v1b = smem_u32(V1) + scb * 4;

    // y init = v0 (read back from V0, 16B-aligned pairs).
    u64 y[2][4];
    #pragma unroll
    for (int r = 0; r < 2; r++) {
        uint32_t rb = v0b + (d0 + r) * 144;
        asm("ld.shared.v2.b64 {%0, %1}, [%2];"      : "=l"(y[r][0]), "=l"(y[r][1]) : "r"(rb));
        asm("ld.shared.v2.b64 {%0, %1}, [%2 + 16];" : "=l"(y[r][2]), "=l"(y[r][3]) : "r"(rb));
    }

    uint32_t vcb = v0b, vnb = v1b;

    #pragma unroll 1
    for (int k = 1; k <= KTERMS; k++) {
        u64 acc[2][4];
        #pragma unroll
        for (int p = 0; p < 4; p++) { acc[0][p] = 0ull; acc[1][p] = 0ull; }

        #pragma unroll 16
        for (int j = 0; j < Dd; j++) {
            float w0, w1;
            asm("ld.shared.v2.f32 {%0, %1}, [%2];"
                : "=f"(w0), "=f"(w1) : "r"(wb + j * (WP * 4)));
            u64 va, vb, vc, vd;
            asm("ld.shared.v2.b64 {%0, %1}, [%2];"
                : "=l"(va), "=l"(vb) : "r"(vcb + j * (VP * 4)));
            asm("ld.shared.v2.b64 {%0, %1}, [%2 + 16];"
                : "=l"(vc), "=l"(vd) : "r"(vcb + j * (VP * 4)));
            u64 w0d = pk2(w0, w0), w1d = pk2(w1, w1);
            acc[0][0] = fma2(va, w0d, acc[0][0]);
            acc[0][1] = fma2(vb, w0d, acc[0][1]);
            acc[0][2] = fma2(vc, w0d, acc[0][2]);
            acc[0][3] = fma2(vd, w0d, acc[0][3]);
            acc[1][0] = fma2(va, w1d, acc[1][0]);
            acc[1][1] = fma2(vb, w1d, acc[1][1]);
            acc[1][2] = fma2(vc, w1d, acc[1][2]);
            acc[1][3] = fma2(vd, w1d, acc[1][3]);
        }

        // v_k = (t/k) u ; y += v_k ; store as next operand.
        float invk = 1.0f / (float)k;
        u64 ikd = pk2(invk, invk);
        u64 scp[4];
        #pragma unroll
        for (int p = 0; p < 4; p++) scp[p] = mul2(tp[p], ikd);

        u64 v[2][4];
        #pragma unroll
        for (int r = 0; r < 2; r++)
            #pragma unroll
            for (int p = 0; p < 4; p++) {
                v[r][p] = mul2(acc[r][p], scp[p]);
                y[r][p] = add2(y[r][p], v[r][p]);
            }

        if (k < KTERMS) {
            #pragma unroll
            for (int r = 0; r < 2; r++) {
                uint32_t rb = vnb + (d0 + r) * 144;
                asm volatile("st.shared.v2.b64 [%0], {%1, %2};"
                             :: "r"(rb), "l"(v[r][0]), "l"(v[r][1]) : "memory");
                asm volatile("st.shared.v2.b64 [%0 + 16], {%1, %2};"
                             :: "r"(rb), "l"(v[r][2]), "l"(v[r][3]) : "memory");
            }
            __syncthreads();
            uint32_t tmp = vcb; vcb = vnb; vnb = tmp;
        }
    }

    // Epilogue: out = [y + bias*t | diag(W)*t], each [B, D].
    float b0 = bias[d0], b1 = bias[d0 + 1];
    float w00 = W[(size_t)d0 * Dd + d0];
    float w11 = W[(size_t)(d0 + 1) * Dd + d0 + 1];
    u64 bd0 = pk2(b0, b0), bd1 = pk2(b1, b1);

    #pragma unroll
    for (int p = 0; p < 4; p++) {
        u64 y0 = fma2(bd0, tp[p], y[0][p]);   // row d0:   (s_even, s_odd)
        u64 y1 = fma2(bd1, tp[p], y[1][p]);   // row d0+1: (s_even, s_odd)
        float a0, a1, c0, c1, t0, t1;
        upk(y0, a0, a1); upk(y1, c0, c1); upk(tp[p], t0, t1);
        size_t se = (size_t)(s0 + scb + 2 * p);
        // y: warp writes 256B contiguous per sample (rows 2l..2l+1 per lane).
        *(float2*)&out[se * Dd + d0]       = make_float2(a0, c0);
        *(float2*)&out[(se + 1) * Dd + d0] = make_float2(a1, c1);
        *(float2*)&out[(size_t)Bb * Dd + se * Dd + d0]       = make_float2(w00 * t0, w11 * t0);
        *(float2*)&out[(size_t)Bb * Dd + (se + 1) * Dd + d0] = make_float2(w00 * t1, w11 * t1);
    }
}

extern "C" void kernel_launch(void* const* d_in, const int* in_sizes, int n_in,
                              void* d_out, int out_size) {
    const float* x    = (const float*)d_in[0];
    const float* t    = (const float*)d_in[1];
    const float* W    = (const float*)d_in[2];
    const float* bias = (const float*)d_in[3];
    float* out = (float*)d_out;

    size_t smem = (Dd * WP + 2 * Dd * VP + 64) * sizeof(float);  // ~104.7 KB
    cudaFuncSetAttribute(affexp_kernel,
                         cudaFuncAttributeMaxDynamicSharedMemorySize, (int)smem);
    affexp_kernel<<<Bb / NT, NTHREADS, smem>>>(x, t, W, bias, out);
}

// round 7
// speedup vs baseline: 3.9532x; 1.6888x over previous
#include <cuda_runtime.h>
#include <cuda_bf16.h>
#include <cstdint>

#define Dd 128
#define Bb 4096
#define NT 32            // samples per CTA
#define NTHREADS 256     // 8 warps; warp w owns rows [16w, 16w+16)
#define KTERMS 11        // Taylor terms; bf16-split err ~1.5e-5 dominates
#define WFP 132          // Wf f32 pitch (reduces extraction conflicts)
#define XFP 132
#define PW  136          // V operand pitch in u32 words (136%32==8 -> cf B loads)

// ---- shared memory byte offsets ----
#define OFF_WF  0                         // W f32 staging        67584 B
#define OFF_XF  (OFF_WF + 128*WFP*4)      // x tile f32           16896 B
#define OFF_TS  (OFF_XF + 32*XFP*4)       // t values               128 B
#define OFF_WD  (OFF_TS + 128)            // diag(W)                512 B
#define OFF_VC0 (OFF_WD + 512)            // V operand buf0       17408 B
#define OFF_VC1 (OFF_VC0 + 32*PW*4)       // V operand buf1       17408 B
#define SMEM_TOTAL (OFF_VC1 + 32*PW*4)    // 119936 B
// V operand layout: u32 word[s*PW + j] (j even) = (vhi[j], vhi[j+1]),
//                   word[s*PW + j + 1]          = (vlo[j], vlo[j+1]).
// One ld.shared.v2.b32 fetches the hi and lo B-fragment halves together.

static __device__ __forceinline__ uint32_t smem_u32(const void* p) {
    uint32_t a;
    asm("{ .reg .u64 t; cvta.to.shared.u64 t, %1; cvt.u32.u64 %0, t; }" : "=r"(a) : "l"(p));
    return a;
}
// m16n8k16 row.col bf16 -> f32, D accumulates in place.
static __device__ __forceinline__ void mma16816(float* c, const uint32_t* a,
                                                uint32_t b0, uint32_t b1) {
    asm("mma.sync.aligned.m16n8k16.row.col.f32.bf16.bf16.f32 "
        "{%0,%1,%2,%3}, {%4,%5,%6,%7}, {%8,%9}, {%0,%1,%2,%3};"
        : "+f"(c[0]), "+f"(c[1]), "+f"(c[2]), "+f"(c[3])
        : "r"(a[0]), "r"(a[1]), "r"(a[2]), "r"(a[3]), "r"(b0), "r"(b1));
}
static __device__ __forceinline__ uint16_t bf16_hi(float v) {
    uint16_t h; asm("cvt.rn.bf16.f32 %0, %1;" : "=h"(h) : "f"(v)); return h;
}
static __device__ __forceinline__ void split2(float v, uint16_t& h, uint16_t& l) {
    h = bf16_hi(v);
    float rem = v - __uint_as_float((uint32_t)h << 16);
    l = bf16_hi(rem);
}
static __device__ __forceinline__ uint32_t pkh(uint16_t a, uint16_t b) {
    return (uint32_t)a | ((uint32_t)b << 16);
}

// y_b = exp(t_b W) x_b + bias t_b ; ljd = diag(W) t_b.
// Taylor v_k = (t_b/k) W v_{k-1} on tensor cores: W = Whi+Wlo (bf16) held in
// REGISTERS across all iterations; u = Whi vhi + Whi vlo + Wlo vhi (f32 acc).
__global__ void __launch_bounds__(NTHREADS, 1) affexp_mma_kernel(
    const float* __restrict__ x, const float* __restrict__ t,
    const float* __restrict__ W, const float* __restrict__ bias,
    float* __restrict__ out)
{
    extern __shared__ char smc[];
    float* Wf = (float*)(smc + OFF_WF);
    float* Xf = (float*)(smc + OFF_XF);
    float* ts = (float*)(smc + OFF_TS);
    float* wd = (float*)(smc + OFF_WD);

    const int tid = threadIdx.x;
    const int w   = tid >> 5;
    const int l   = tid & 31;
    const int g   = l >> 2;        // groupID: rows m0+g, m0+g+8 / B col n0+g
    const int tq  = l & 3;         // k pairs 2tq, 2tq+8 / C cols 2tq, 2tq+1
    const int m0  = w * 16;
    const int s0  = blockIdx.x * NT;

    // ---- prologue: stage W, x, t in smem (coalesced) ----
    for (int idx = tid; idx < Dd * Dd; idx += NTHREADS) {
        int i = idx >> 7, j = idx & 127;
        Wf[i * WFP + j] = W[idx];
    }
    for (int idx = tid; idx < NT * Dd; idx += NTHREADS) {
        int s = idx >> 7, d = idx & 127;
        Xf[s * XFP + d] = x[(size_t)(s0 + s) * Dd + d];
    }
    if (tid < NT) ts[tid] = t[s0 + tid];
    __syncthreads();
    if (tid < Dd) wd[tid] = Wf[tid * WFP + tid];

    // ---- A fragments (W hi/lo) in registers, 8 k-tiles ----
    uint32_t Ahi[8][4], Alo[8][4];
    #pragma unroll
    for (int kt = 0; kt < 8; kt++) {
        int k0 = kt * 16;
        #pragma unroll
        for (int rr = 0; rr < 2; rr++) {          // rows m0+g, m0+g+8
            int r = m0 + g + 8 * rr;
            #pragma unroll
            for (int kh = 0; kh < 2; kh++) {      // k halves +0, +8
                float2 p = *(const float2*)&Wf[r * WFP + k0 + 2 * tq + 8 * kh];
                uint16_t h0, l0, h1, l1;
                split2(p.x, h0, l0);
                split2(p.y, h1, l1);
                Ahi[kt][2 * kh + rr] = pkh(h0, h1);
                Alo[kt][2 * kh + rr] = pkh(l0, l1);
            }
        }
    }

    // ---- y init = v0 = x, in C-fragment layout; t per column ----
    float y[16], tc[8];
    #pragma unroll
    for (int nt = 0; nt < 4; nt++) {
        int n0 = 8 * nt;
        tc[nt * 2 + 0] = ts[n0 + 2 * tq];
        tc[nt * 2 + 1] = ts[n0 + 2 * tq + 1];
        y[nt * 4 + 0] = Xf[(n0 + 2 * tq) * XFP + m0 + g];
        y[nt * 4 + 1] = Xf[(n0 + 2 * tq + 1) * XFP + m0 + g];
        y[nt * 4 + 2] = Xf[(n0 + 2 * tq) * XFP + m0 + g + 8];
        y[nt * 4 + 3] = Xf[(n0 + 2 * tq + 1) * XFP + m0 + g + 8];
    }

    // ---- v0 -> operand buffer 0 (split to bf16 hi/lo) ----
    for (int idx = tid; idx < NT * Dd; idx += NTHREADS) {
        int s = idx >> 7, d = idx & 127;
        uint16_t h, lo16;
        split2(Xf[s * XFP + d], h, lo16);
        char* row = smc + OFF_VC0 + s * (PW * 4);
        int jp = d & ~1, hw = d & 1;
        *(uint16_t*)(row + jp * 4 + hw * 2)     = h;
        *(uint16_t*)(row + jp * 4 + 4 + hw * 2) = lo16;
    }
    __syncthreads();

    const uint32_t vc0 = smem_u32(smc + OFF_VC0);
    const uint32_t vc1 = smem_u32(smc + OFF_VC1);

    #pragma unroll 1
    for (int k = 1; k <= KTERMS; k++) {
        const uint32_t vcur = (k & 1) ? vc0 : vc1;
        const uint32_t vnxt = (k & 1) ? vc1 : vc0;

        float C[16];
        #pragma unroll
        for (int c = 0; c < 16; c++) C[c] = 0.0f;

        #pragma unroll
        for (int kt = 0; kt < 8; kt++) {
            int k0 = kt * 16;
            #pragma unroll
            for (int nt = 0; nt < 4; nt++) {
                uint32_t rb = vcur + ((8 * nt + g) * PW + k0 + 2 * tq) * 4;
                uint32_t bh0, bl0, bh1, bl1;
                asm("ld.shared.v2.b32 {%0,%1}, [%2];"      : "=r"(bh0), "=r"(bl0) : "r"(rb));
                asm("ld.shared.v2.b32 {%0,%1}, [%2 + 32];" : "=r"(bh1), "=r"(bl1) : "r"(rb));
                mma16816(&C[nt * 4], Ahi[kt], bh0, bh1);
                mma16816(&C[nt * 4], Alo[kt], bh0, bh1);
                mma16816(&C[nt * 4], Ahi[kt], bl0, bl1);
            }
        }

        // v = (t/k) u ; y += v ; re-split v as next B operand.
        float invk = 1.0f / (float)k;
        if (k < KTERMS) {
            #pragma unroll
            for (int nt = 0; nt < 4; nt++) {
                float sc0 = tc[nt * 2] * invk, sc1 = tc[nt * 2 + 1] * invk;
                #pragma unroll
                for (int c = 0; c < 4; c++) {
                    float v = C[nt * 4 + c] * ((c & 1) ? sc1 : sc0);
                    y[nt * 4 + c] += v;
                    int s = 8 * nt + 2 * tq + (c & 1);
                    int d = m0 + g + 8 * (c >> 1);
                    uint16_t h, lo16;
                    split2(v, h, lo16);
                    uint32_t row = vnxt + s * (PW * 4);
                    int jp = d & ~1, hw = d & 1;
                    asm volatile("st.shared.b16 [%0], %1;" :: "r"(row + jp * 4 + hw * 2), "h"(h) : "memory");
                    asm volatile("st.shared.b16 [%0], %1;" :: "r"(row + jp * 4 + 4 + hw * 2), "h"(lo16) : "memory");
                }
            }
            __syncthreads();
        } else {
            #pragma unroll
            for (int nt = 0; nt < 4; nt++) {
                float sc0 = tc[nt * 2] * invk, sc1 = tc[nt * 2 + 1] * invk;
                #pragma unroll
                for (int c = 0; c < 4; c++)
                    y[nt * 4 + c] += C[nt * 4 + c] * ((c & 1) ? sc1 : sc0);
            }
        }
    }

    // ---- epilogue: out = [y + bias*t | diag(W)*t], each [B, D] ----
    float b0 = bias[m0 + g], b1 = bias[m0 + g + 8];
    #pragma unroll
    for (int nt = 0; nt < 4; nt++) {
        #pragma unroll
        for (int c = 0; c < 4; c++) {
            int sG = s0 + 8 * nt + 2 * tq + (c & 1);
            int d  = m0 + g + 8 * (c >> 1);
            float bb = (c >> 1) ? b1 : b0;
            out[(size_t)sG * Dd + d] = y[nt * 4 + c] + bb * tc[nt * 2 + (c & 1)];
        }
    }
    for (int idx = tid; idx < NT * Dd; idx += NTHREADS) {
        int s = idx >> 7, d = idx & 127;
        out[(size_t)Bb * Dd + (size_t)(s0 + s) * Dd + d] = wd[d] * ts[s];
    }
}

extern "C" void kernel_launch(void* const* d_in, const int* in_sizes, int n_in,
                              void* d_out, int out_size) {
    const float* x    = (const float*)d_in[0];
    const float* t    = (const float*)d_in[1];
    const float* W    = (const float*)d_in[2];
    const float* bias = (const float*)d_in[3];
    float* out = (float*)d_out;

    cudaFuncSetAttribute(affexp_mma_kernel,
                         cudaFuncAttributeMaxDynamicSharedMemorySize, SMEM_TOTAL);
    affexp_mma_kernel<<<Bb / NT, NTHREADS, SMEM_TOTAL>>>(x, t, W, bias, out);
}

// round 8
// speedup vs baseline: 4.5987x; 1.1633x over previous
#include <cuda_runtime.h>
#include <cuda_bf16.h>
#include <cstdint>

#define Dd 128
#define Bb 4096
#define NT 32            // samples per CTA
#define NTHREADS 512     // 16 warps: 8 row-strips x 2 sample-halves; 4 warps/SMSP
#define KTERMS 10        // Taylor terms; truncation ~5e-5, bf16-split ~1e-5
#define WFP 132          // Wf f32 pitch
#define XFP 132
#define PW  136          // V operand pitch in u32 words

// ---- shared memory byte offsets ----
#define OFF_WF  0                         // W f32 staging        67584 B
#define OFF_XF  (OFF_WF + 128*WFP*4)      // x tile f32           16896 B
#define OFF_TS  (OFF_XF + 32*XFP*4)       // t values               128 B
#define OFF_WD  (OFF_TS + 128)            // diag(W)                512 B
#define OFF_VC0 (OFF_WD + 512)            // V operand buf0       17408 B
#define OFF_VC1 (OFF_VC0 + 32*PW*4)       // V operand buf1       17408 B
#define SMEM_TOTAL (OFF_VC1 + 32*PW*4)    // 119936 B
// V operand layout (verified R7): u32 word[s*PW + j] (j even) = (vhi[j], vhi[j+1]),
//                                 word[s*PW + j + 1]          = (vlo[j], vlo[j+1]).

static __device__ __forceinline__ uint32_t smem_u32(const void* p) {
    uint32_t a;
    asm("{ .reg .u64 t; cvta.to.shared.u64 t, %1; cvt.u32.u64 %0, t; }" : "=r"(a) : "l"(p));
    return a;
}
static __device__ __forceinline__ void mma16816(float* c, const uint32_t* a,
                                                uint32_t b0, uint32_t b1) {
    asm("mma.sync.aligned.m16n8k16.row.col.f32.bf16.bf16.f32 "
        "{%0,%1,%2,%3}, {%4,%5,%6,%7}, {%8,%9}, {%0,%1,%2,%3};"
        : "+f"(c[0]), "+f"(c[1]), "+f"(c[2]), "+f"(c[3])
        : "r"(a[0]), "r"(a[1]), "r"(a[2]), "r"(a[3]), "r"(b0), "r"(b1));
}
static __device__ __forceinline__ uint16_t bf16_hi(float v) {
    uint16_t h; asm("cvt.rn.bf16.f32 %0, %1;" : "=h"(h) : "f"(v)); return h;
}
static __device__ __forceinline__ void split2(float v, uint16_t& h, uint16_t& l) {
    h = bf16_hi(v);
    float rem = v - __uint_as_float((uint32_t)h << 16);
    l = bf16_hi(rem);
}
static __device__ __forceinline__ uint32_t pkh(uint16_t a, uint16_t b) {
    return (uint32_t)a | ((uint32_t)b << 16);
}

// y_b = exp(t_b W) x_b + bias t_b ; ljd = diag(W) t_b.
// Taylor v_k = (t_b/k) W v_{k-1} on tensor cores (bf16 hi/lo error split,
// W fragments register-resident). 16 warps -> 4 independent streams/SMSP
// to cover the serial mma->epilogue->sync chain latency.
__global__ void __launch_bounds__(NTHREADS, 1) affexp_mma_kernel(
    const float* __restrict__ x, const float* __restrict__ t,
    const float* __restrict__ W, const float* __restrict__ bias,
    float* __restrict__ out)
{
    extern __shared__ char smc[];
    float* Wf = (float*)(smc + OFF_WF);
    float* Xf = (float*)(smc + OFF_XF);
    float* ts = (float*)(smc + OFF_TS);
    float* wd = (float*)(smc + OFF_WD);

    const int tid = threadIdx.x;
    const int w    = tid >> 5;
    const int l    = tid & 31;
    const int g    = l >> 2;        // rows m0+g, m0+g+8 / B sample-within-8 g
    const int tq   = l & 3;         // k pairs / C cols 2tq, 2tq+1
    const int m0   = (w >> 1) * 16; // row strip
    const int nbas = (w & 1) * 16;  // sample half
    const int s0   = blockIdx.x * NT;

    // ---- prologue: stage W, x, t in smem (coalesced) ----
    for (int idx = tid; idx < Dd * Dd; idx += NTHREADS) {
        int i = idx >> 7, j = idx & 127;
        Wf[i * WFP + j] = W[idx];
    }
    for (int idx = tid; idx < NT * Dd; idx += NTHREADS) {
        int s = idx >> 7, d = idx & 127;
        Xf[s * XFP + d] = x[(size_t)(s0 + s) * Dd + d];
    }
    if (tid < NT) ts[tid] = t[s0 + tid];
    __syncthreads();
    if (tid < Dd) wd[tid] = Wf[tid * WFP + tid];

    // ---- A fragments (W hi/lo) in registers, 8 k-tiles ----
    uint32_t Ahi[8][4], Alo[8][4];
    #pragma unroll
    for (int kt = 0; kt < 8; kt++) {
        int k0 = kt * 16;
        #pragma unroll
        for (int rr = 0; rr < 2; rr++) {
            int r = m0 + g + 8 * rr;
            #pragma unroll
            for (int kh = 0; kh < 2; kh++) {
                float2 p = *(const float2*)&Wf[r * WFP + k0 + 2 * tq + 8 * kh];
                uint16_t h0, l0, h1, l1;
                split2(p.x, h0, l0);
                split2(p.y, h1, l1);
                Ahi[kt][2 * kh + rr] = pkh(h0, h1);
                Alo[kt][2 * kh + rr] = pkh(l0, l1);
            }
        }
    }

    // ---- y init = v0 = x in C-fragment layout; t per column ----
    float y[8], tc[4];
    #pragma unroll
    for (int nt = 0; nt < 2; nt++) {
        int n0 = nbas + 8 * nt;
        tc[nt * 2 + 0] = ts[n0 + 2 * tq];
        tc[nt * 2 + 1] = ts[n0 + 2 * tq + 1];
        y[nt * 4 + 0] = Xf[(n0 + 2 * tq) * XFP + m0 + g];
        y[nt * 4 + 1] = Xf[(n0 + 2 * tq + 1) * XFP + m0 + g];
        y[nt * 4 + 2] = Xf[(n0 + 2 * tq) * XFP + m0 + g + 8];
        y[nt * 4 + 3] = Xf[(n0 + 2 * tq + 1) * XFP + m0 + g + 8];
    }

    // ---- v0 -> operand buffer 0 (split to bf16 hi/lo) ----
    for (int idx = tid; idx < NT * Dd; idx += NTHREADS) {
        int s = idx >> 7, d = idx & 127;
        uint16_t h, lo16;
        split2(Xf[s * XFP + d], h, lo16);
        char* row = smc + OFF_VC0 + s * (PW * 4);
        int jp = d & ~1, hw = d & 1;
        *(uint16_t*)(row + jp * 4 + hw * 2)     = h;
        *(uint16_t*)(row + jp * 4 + 4 + hw * 2) = lo16;
    }
    __syncthreads();

    const uint32_t vc0 = smem_u32(smc + OFF_VC0);
    const uint32_t vc1 = smem_u32(smc + OFF_VC1);

    #pragma unroll 1
    for (int k = 1; k <= KTERMS; k++) {
        const uint32_t vcur = (k & 1) ? vc0 : vc1;
        const uint32_t vnxt = (k & 1) ? vc1 : vc0;

        float C[8];
        #pragma unroll
        for (int c = 0; c < 8; c++) C[c] = 0.0f;

        #pragma unroll
        for (int kt = 0; kt < 8; kt++) {
            int k0 = kt * 16;
            #pragma unroll
            for (int nt = 0; nt < 2; nt++) {
                uint32_t rb = vcur + ((nbas + 8 * nt + g) * PW + k0 + 2 * tq) * 4;
                uint32_t bh0, bl0, bh1, bl1;
                asm("ld.shared.v2.b32 {%0,%1}, [%2];"      : "=r"(bh0), "=r"(bl0) : "r"(rb));
                asm("ld.shared.v2.b32 {%0,%1}, [%2 + 32];" : "=r"(bh1), "=r"(bl1) : "r"(rb));
                mma16816(&C[nt * 4], Ahi[kt], bh0, bh1);
                mma16816(&C[nt * 4], Alo[kt], bh0, bh1);
                mma16816(&C[nt * 4], Ahi[kt], bl0, bl1);
            }
        }

        // v = (t/k) u ; y += v ; re-split as next B operand.
        float invk = 1.0f / (float)k;
        if (k < KTERMS) {
            #pragma unroll
            for (int nt = 0; nt < 2; nt++) {
                float sc0 = tc[nt * 2] * invk, sc1 = tc[nt * 2 + 1] * invk;
                #pragma unroll
                for (int c = 0; c < 4; c++) {
                    float v = C[nt * 4 + c] * ((c & 1) ? sc1 : sc0);
                    y[nt * 4 + c] += v;
                    int s = nbas + 8 * nt + 2 * tq + (c & 1);
                    int d = m0 + g + 8 * (c >> 1);
                    uint16_t h, lo16;
                    split2(v, h, lo16);
                    uint32_t row = vnxt + s * (PW * 4);
                    int jp = d & ~1, hw = d & 1;
                    asm volatile("st.shared.b16 [%0], %1;" :: "r"(row + jp * 4 + hw * 2), "h"(h) : "memory");
                    asm volatile("st.shared.b16 [%0], %1;" :: "r"(row + jp * 4 + 4 + hw * 2), "h"(lo16) : "memory");
                }
            }
            __syncthreads();
        } else {
            #pragma unroll
            for (int nt = 0; nt < 2; nt++) {
                float sc0 = tc[nt * 2] * invk, sc1 = tc[nt * 2 + 1] * invk;
                #pragma unroll
                for (int c = 0; c < 4; c++)
                    y[nt * 4 + c] += C[nt * 4 + c] * ((c & 1) ? sc1 : sc0);
            }
        }
    }

    // ---- epilogue: out = [y + bias*t | diag(W)*t], each [B, D] ----
    float b0 = bias[m0 + g], b1 = bias[m0 + g + 8];
    #pragma unroll
    for (int nt = 0; nt < 2; nt++) {
        #pragma unroll
        for (int c = 0; c < 4; c++) {
            int sG = s0 + nbas + 8 * nt + 2 * tq + (c & 1);
            int d  = m0 + g + 8 * (c >> 1);
            float bb = (c >> 1) ? b1 : b0;
            out[(size_t)sG * Dd + d] = y[nt * 4 + c] + bb * tc[nt * 2 + (c & 1)];
        }
    }
    for (int idx = tid; idx < NT * Dd; idx += NTHREADS) {
        int s = idx >> 7, d = idx & 127;
        out[(size_t)Bb * Dd + (size_t)(s0 + s) * Dd + d] = wd[d] * ts[s];
    }
}

extern "C" void kernel_launch(void* const* d_in, const int* in_sizes, int n_in,
                              void* d_out, int out_size) {
    const float* x    = (const float*)d_in[0];
    const float* t    = (const float*)d_in[1];
    const float* W    = (const float*)d_in[2];
    const float* bias = (const float*)d_in[3];
    float* out = (float*)d_out;

    cudaFuncSetAttribute(affexp_mma_kernel,
                         cudaFuncAttributeMaxDynamicSharedMemorySize, SMEM_TOTAL);
    affexp_mma_kernel<<<Bb / NT, NTHREADS, SMEM_TOTAL>>>(x, t, W, bias, out);
}